// round 12
// baseline (speedup 1.0000x reference)
#include <cuda_runtime.h>
#include <cuda_fp16.h>
#include <math.h>
#include <stdint.h>

#define NN 100000
#define EE 3200000
#define NHID 256
#define NCLASS 16
#define SCAN_BLK 1024
#define NSCANBLK ((NN + SCAN_BLK - 1) / SCAN_BLK)   // 98

// ---------------- scratch (static device globals) ---------------------------
__device__ __half g_Xh[(size_t)NN * 128];   // x in fp16
__device__ __half g_HA[(size_t)NN * 256];   // activation ping (fp16, scaled)
__device__ __half g_HB[(size_t)NN * 256];   // activation pong (fp16, scaled)
__device__ int2   g_cv[EE];                 // packed (col, val) CSR payload
__device__ int    g_rowptr[NN + 1];
__device__ int    g_cursor[NN];
__device__ int    g_blocksums[SCAN_BLK];
__device__ __half g_Wh1[256 * 128];         // weights [n][k] K-major fp16
__device__ __half g_Wh2[256 * 256];
__device__ __half g_Wh3[256 * 256];
__device__ __half g_Wh4[256 * 256];
__device__ __half g_fwT[16 * 256];          // fc_w transposed [n][k] fp16

__device__ __forceinline__ uint32_t smem_u32(const void* p) {
    uint32_t a;
    asm("{ .reg .u64 t; cvta.to.shared.u64 t, %1; cvt.u32.u64 %0, t; }"
        : "=r"(a) : "l"(p));
    return a;
}

__device__ __forceinline__ void cpasync16(uint32_t dst, const void* src) {
    asm volatile("cp.async.ca.shared.global [%0], [%1], 16;" :: "r"(dst), "l"(src));
}

// ---------------- prep: fp16 conversions + cursor zero -----------------------
#define PREP_W1   (256 * 128)
#define PREP_W    (256 * 256)
#define PREP_FW   (16 * 256)
#define PREP_X4   ((long long)NN * 128 / 4)
#define PREP_TOTAL (PREP_W1 + 3LL * PREP_W + PREP_FW + PREP_X4 + NN)

__global__ void k_prep(const float* __restrict__ x,
                       const float* __restrict__ w1, const float* __restrict__ w2,
                       const float* __restrict__ w3, const float* __restrict__ w4,
                       const float* __restrict__ fcw) {
    long long i = (long long)blockIdx.x * blockDim.x + threadIdx.x;
    if (i < PREP_W1) {
        int n = (int)(i / 128), k = (int)(i % 128);
        g_Wh1[i] = __float2half_rn(w1[k * 256 + n]);
        return;
    }
    i -= PREP_W1;
    if (i < 3 * PREP_W) {
        int w = (int)(i / PREP_W);
        int r = (int)(i % PREP_W);
        int n = r / 256, k = r % 256;
        if (w == 0) g_Wh2[r] = __float2half_rn(w2[k * 256 + n]);
        else if (w == 1) g_Wh3[r] = __float2half_rn(w3[k * 256 + n]);
        else g_Wh4[r] = __float2half_rn(w4[k * 256 + n]);
        return;
    }
    i -= 3 * PREP_W;
    if (i < PREP_FW) {
        int n = (int)(i / 256), k = (int)(i % 256);
        g_fwT[i] = __float2half_rn(fcw[k * 16 + n]);
        return;
    }
    i -= PREP_FW;
    if (i < PREP_X4) {
        float4 v = ((const float4*)x)[i];
        __half2 h0 = __floats2half2_rn(v.x, v.y);
        __half2 h1 = __floats2half2_rn(v.z, v.w);
        ((uint2*)g_Xh)[i] = make_uint2(*(uint32_t*)&h0, *(uint32_t*)&h1);
        return;
    }
    i -= PREP_X4;
    if (i < NN) g_cursor[i] = 0;
}

// ---------------- CSR build --------------------------------------------------
__global__ void k_hist(const int* __restrict__ row) {
    int e = blockIdx.x * blockDim.x + threadIdx.x;
    if (e < EE) atomicAdd(&g_cursor[row[e]], 1);
}

__global__ void k_scan1() {
    __shared__ int s[SCAN_BLK];
    int t = threadIdx.x;
    int gid = blockIdx.x * SCAN_BLK + t;
    s[t] = (gid < NN) ? g_cursor[gid] : 0;
    for (int d = 1; d < SCAN_BLK; d <<= 1) {
        __syncthreads();
        int u = (t >= d) ? s[t - d] : 0;
        __syncthreads();
        s[t] += u;
    }
    __syncthreads();
    if (gid < NN) g_rowptr[gid + 1] = s[t];
    if (t == SCAN_BLK - 1) g_blocksums[blockIdx.x] = s[t];
}

__global__ void k_scan2() {
    __shared__ int s[128];
    int t = threadIdx.x;
    s[t] = (t < NSCANBLK) ? g_blocksums[t] : 0;
    for (int d = 1; d < 128; d <<= 1) {
        __syncthreads();
        int u = (t >= d) ? s[t - d] : 0;
        __syncthreads();
        s[t] += u;
    }
    __syncthreads();
    if (t < NSCANBLK) g_blocksums[t] = s[t];
}

__global__ void k_scan3cur() {
    int i = blockIdx.x * blockDim.x + threadIdx.x;
    if (i < NN) {
        int b = i >> 10;
        int off = b ? g_blocksums[b - 1] : 0;
        int v = g_rowptr[i + 1] + off;
        g_rowptr[i + 1] = v;
        if (i + 1 < NN) g_cursor[i + 1] = v;
        if (i == 0) { g_rowptr[0] = 0; g_cursor[0] = 0; }
    }
}

__global__ void k_scatter(const int* __restrict__ row, const int* __restrict__ col,
                          const float* __restrict__ val) {
    int e = blockIdx.x * blockDim.x + threadIdx.x;
    if (e < EE) {
        int r = row[e];
        int p = atomicAdd(&g_cursor[r], 1);
        g_cv[p] = make_int2(col[e], __float_as_int(val[e]));
    }
}

// ---------------- FUSED layer: SpMM gather -> SMEM A -> HMMA GEMM ------------
// CTA = 256 threads, 128 dest nodes. S (input) and C (output) MUST be distinct.
#define HROW 72                        // B stage row: 64 halves + 8 pad
#define HTILE_HALVES (128 * HROW)      // 9216 halves per B buffer

template <int KDIM>
__global__ void __launch_bounds__(256, 2) k_fused(
    const __half* __restrict__ S, const __half* __restrict__ Wt,
    const float* __restrict__ bias, float bscale, __half* __restrict__ C) {
    constexpr int AROW = KDIM + 8;            // halves per A row (pad keeps banks)
    constexpr int ABASE = 128 * AROW;         // B region offset (halves)
    constexpr int NITER = KDIM / 64;
    extern __shared__ __half sm[];
    uint32_t sb = smem_u32(sm);
    int tid = threadIdx.x;
    int wid = tid >> 5, lane = tid & 31;
    int row0 = blockIdx.x * 128;

    // ---------------- phase 1: gather 16 nodes per warp ----------------
    constexpr int HP = KDIM / 32;             // halves per lane (4 or 8)
    for (int i = 0; i < 16; i++) {
        int node = row0 + wid * 16 + i;
        if (node >= NN) break;
        float acc[HP];
#pragma unroll
        for (int p = 0; p < HP; p++) acc[p] = 0.f;

        int s = g_rowptr[node], e = g_rowptr[node + 1];
        for (int base = s; base < e; base += 32) {
            int idx = base + lane;
            int c = 0;
            float v = 0.f;
            if (idx < e) {
                int2 q = g_cv[idx];
                c = q.x;
                v = __int_as_float(q.y);
            }
            int m = min(32, e - base);
#pragma unroll 8
            for (int j = 0; j < 32; j++) {
                if (j >= m) break;
                int cj = __shfl_sync(0xffffffffu, c, j);
                float vj = __shfl_sync(0xffffffffu, v, j);
                if (KDIM == 256) {
                    uint4 q = ((const uint4*)S)[(size_t)cj * 32 + lane];
                    const __half2* h = (const __half2*)&q;
#pragma unroll
                    for (int p = 0; p < 4; p++) {
                        float2 f = __half22float2(h[p]);
                        acc[p * 2] += vj * f.x;
                        acc[p * 2 + 1] += vj * f.y;
                    }
                } else {
                    uint2 q = ((const uint2*)S)[(size_t)cj * 32 + lane];
                    const __half2* h = (const __half2*)&q;
#pragma unroll
                    for (int p = 0; p < 2; p++) {
                        float2 f = __half22float2(h[p]);
                        acc[p * 2] += vj * f.x;
                        acc[p * 2 + 1] += vj * f.y;
                    }
                }
            }
        }
        // write scaled fp16 row into SMEM A
        const float SC = 0.25f;
        __half2 o[HP / 2];
#pragma unroll
        for (int p = 0; p < HP / 2; p++)
            o[p] = __floats2half2_rn(acc[p * 2] * SC, acc[p * 2 + 1] * SC);
        __half* dst = sm + (wid * 16 + i) * AROW + lane * HP;
        if (KDIM == 256)
            *(uint4*)dst = *(uint4*)o;
        else
            *(uint2*)dst = *(uint2*)o;
    }
    __syncthreads();

    // ---------------- phase 2: GEMM from SMEM A, two N-halves ----------------
    int wm = wid & 1, wn = wid >> 1;          // 2M x 4N warps, warp tile 64x32
    int gid = lane >> 2, tg = lane & 3;
    const uint32_t* As = (const uint32_t*)sm;

    for (int half = 0; half < 2; half++) {
        int col0 = half * 128;

        float acc[4][4][4];
#pragma unroll
        for (int i = 0; i < 4; i++)
#pragma unroll
            for (int j = 0; j < 4; j++)
#pragma unroll
                for (int k = 0; k < 4; k++) acc[i][j][k] = 0.f;

        auto stageB = [&](int c, int buf) {
            const __half* Bg = Wt + (size_t)col0 * KDIM + c * 64;
#pragma unroll
            for (int it = 0; it < 4; it++) {
                int idx = tid + it * 256;
                int r = idx >> 3, c8 = idx & 7;
                cpasync16(sb + (uint32_t)(ABASE + buf * HTILE_HALVES + r * HROW) * 2
                              + c8 * 16,
                          Bg + (size_t)r * KDIM + c8 * 8);
            }
            asm volatile("cp.async.commit_group;" ::: "memory");
        };

        stageB(0, 0);

        for (int c = 0; c < NITER; c++) {
            int buf = c & 1;
            if (c + 1 < NITER) {
                stageB(c + 1, buf ^ 1);
                asm volatile("cp.async.wait_group 1;" ::: "memory");
            } else {
                asm volatile("cp.async.wait_group 0;" ::: "memory");
            }
            __syncthreads();

            const uint32_t* Bs =
                (const uint32_t*)(sm + ABASE + buf * HTILE_HALVES);

#pragma unroll
            for (int ks = 0; ks < 4; ks++) {
                uint32_t a[4][4], b[4][2];
#pragma unroll
                for (int mt = 0; mt < 4; mt++) {
                    int rb = wm * 64 + mt * 16 + gid;
                    int base0 = rb * (AROW / 2) + c * 32 + ks * 8;
                    int base1 = (rb + 8) * (AROW / 2) + c * 32 + ks * 8;
                    a[mt][0] = As[base0 + tg];
                    a[mt][1] = As[base1 + tg];
                    a[mt][2] = As[base0 + tg + 4];
                    a[mt][3] = As[base1 + tg + 4];
                }
#pragma unroll
                for (int nt = 0; nt < 4; nt++) {
                    int nb = wn * 32 + nt * 8 + gid;
                    int base = (nb * HROW + ks * 16) >> 1;
                    b[nt][0] = Bs[base + tg];
                    b[nt][1] = Bs[base + tg + 4];
                }
#pragma unroll
                for (int mt = 0; mt < 4; mt++)
#pragma unroll
                    for (int nt = 0; nt < 4; nt++) {
                        float* d = acc[mt][nt];
                        asm volatile(
                            "mma.sync.aligned.m16n8k16.row.col.f32.f16.f16.f32 "
                            "{%0,%1,%2,%3}, {%4,%5,%6,%7}, {%8,%9}, {%0,%1,%2,%3};"
                            : "+f"(d[0]), "+f"(d[1]), "+f"(d[2]), "+f"(d[3])
                            : "r"(a[mt][0]), "r"(a[mt][1]), "r"(a[mt][2]),
                              "r"(a[mt][3]), "r"(b[nt][0]), "r"(b[nt][1]));
                    }
            }
            __syncthreads();
        }

        // epilogue: scaled bias + relu -> fp16
#pragma unroll
        for (int nt = 0; nt < 4; nt++) {
            int cg = col0 + wn * 32 + nt * 8 + tg * 2;
            float bx = bias[cg] * bscale, by = bias[cg + 1] * bscale;
#pragma unroll
            for (int mt = 0; mt < 4; mt++) {
                int rg = row0 + wm * 64 + mt * 16 + gid;
                float* d = acc[mt][nt];
                if (rg < NN) {
                    float v0 = fmaxf(d[0] + bx, 0.f);
                    float v1 = fmaxf(d[1] + by, 0.f);
                    *(__half2*)(C + (size_t)rg * 256 + cg) =
                        __floats2half2_rn(v0, v1);
                }
                if (rg + 8 < NN) {
                    float v2 = fmaxf(d[2] + bx, 0.f);
                    float v3 = fmaxf(d[3] + by, 0.f);
                    *(__half2*)(C + (size_t)(rg + 8) * 256 + cg) =
                        __floats2half2_rn(v2, v3);
                }
            }
        }
    }
}

// ---------------- HMMA FC + log_softmax (fp16 H at scale 1/256) --------------
__global__ void __launch_bounds__(128) k_fc_hmma(const __half* __restrict__ H,
                                                 const float* __restrict__ fb,
                                                 float* __restrict__ out) {
    __shared__ float sfb[16];
    int tid = threadIdx.x;
    if (tid < 16) sfb[tid] = fb[tid];
    __syncthreads();

    int wid = tid >> 5, lane = tid & 31;
    int gid = lane >> 2, tg = lane & 3;
    int row0 = (blockIdx.x * 4 + wid) * 16;
    if (row0 >= NN) return;

    int rA = row0 + gid;
    int rB = row0 + gid + 8;
    int rAc = min(rA, NN - 1);
    int rBc = min(rB, NN - 1);

    float c0[4] = {0.f, 0.f, 0.f, 0.f};
    float c1[4] = {0.f, 0.f, 0.f, 0.f};

    const __half* HA = H + (size_t)rAc * 256;
    const __half* HB = H + (size_t)rBc * 256;
    const __half* W0 = g_fwT + (size_t)gid * 256;
    const __half* W1 = g_fwT + (size_t)(gid + 8) * 256;

#pragma unroll
    for (int kc = 0; kc < 16; kc++) {
        int k = kc * 16;
        uint32_t a0 = *(const uint32_t*)(HA + k + 2 * tg);
        uint32_t a1 = *(const uint32_t*)(HB + k + 2 * tg);
        uint32_t a2 = *(const uint32_t*)(HA + k + 2 * tg + 8);
        uint32_t a3 = *(const uint32_t*)(HB + k + 2 * tg + 8);
        uint32_t b00 = *(const uint32_t*)(W0 + k + 2 * tg);
        uint32_t b01 = *(const uint32_t*)(W0 + k + 2 * tg + 8);
        uint32_t b10 = *(const uint32_t*)(W1 + k + 2 * tg);
        uint32_t b11 = *(const uint32_t*)(W1 + k + 2 * tg + 8);
        asm volatile(
            "mma.sync.aligned.m16n8k16.row.col.f32.f16.f16.f32 "
            "{%0,%1,%2,%3}, {%4,%5,%6,%7}, {%8,%9}, {%0,%1,%2,%3};"
            : "+f"(c0[0]), "+f"(c0[1]), "+f"(c0[2]), "+f"(c0[3])
            : "r"(a0), "r"(a1), "r"(a2), "r"(a3), "r"(b00), "r"(b01));
        asm volatile(
            "mma.sync.aligned.m16n8k16.row.col.f32.f16.f16.f32 "
            "{%0,%1,%2,%3}, {%4,%5,%6,%7}, {%8,%9}, {%0,%1,%2,%3};"
            : "+f"(c1[0]), "+f"(c1[1]), "+f"(c1[2]), "+f"(c1[3])
            : "r"(a0), "r"(a1), "r"(a2), "r"(a3), "r"(b10), "r"(b11));
    }

    float fb0 = sfb[2 * tg], fb1 = sfb[2 * tg + 1];
    float fb2 = sfb[8 + 2 * tg], fb3 = sfb[8 + 2 * tg + 1];

#pragma unroll
    for (int rr = 0; rr < 2; rr++) {
        int row = rr ? rB : rA;
        float v0 = (rr ? c0[2] : c0[0]) * 256.f + fb0;
        float v1 = (rr ? c0[3] : c0[1]) * 256.f + fb1;
        float v2 = (rr ? c1[2] : c1[0]) * 256.f + fb2;
        float v3 = (rr ? c1[3] : c1[1]) * 256.f + fb3;
        float mx = fmaxf(fmaxf(v0, v1), fmaxf(v2, v3));
        mx = fmaxf(mx, __shfl_xor_sync(0xffffffffu, mx, 1));
        mx = fmaxf(mx, __shfl_xor_sync(0xffffffffu, mx, 2));
        float sm = expf(v0 - mx) + expf(v1 - mx) + expf(v2 - mx) + expf(v3 - mx);
        sm += __shfl_xor_sync(0xffffffffu, sm, 1);
        sm += __shfl_xor_sync(0xffffffffu, sm, 2);
        float ls = logf(sm);
        if (row < NN) {
            float* o = out + (size_t)row * 16;
            *(float2*)(o + 2 * tg) = make_float2((v0 - mx) - ls, (v1 - mx) - ls);
            *(float2*)(o + 8 + 2 * tg) = make_float2((v2 - mx) - ls, (v3 - mx) - ls);
        }
    }
}

// ---------------- launch -----------------------------------------------------
extern "C" void kernel_launch(void* const* d_in, const int* in_sizes, int n_in,
                              void* d_out, int out_size) {
    const float* x    = (const float*)d_in[0];
    const float* adj_val = (const float*)d_in[1];
    const float* w1 = (const float*)d_in[2];
    const float* b1 = (const float*)d_in[3];
    const float* w2 = (const float*)d_in[4];
    const float* b2 = (const float*)d_in[5];
    const float* w3 = (const float*)d_in[6];
    const float* b3 = (const float*)d_in[7];
    const float* w4 = (const float*)d_in[8];
    const float* b4 = (const float*)d_in[9];
    const float* fc_w = (const float*)d_in[10];
    const float* fc_b = (const float*)d_in[11];
    const int* adj_row = (const int*)d_in[12];
    const int* adj_col = (const int*)d_in[13];
    float* out = (float*)d_out;

    __half* Xh; cudaGetSymbolAddress((void**)&Xh, g_Xh);
    __half* HA; cudaGetSymbolAddress((void**)&HA, g_HA);
    __half* HB; cudaGetSymbolAddress((void**)&HB, g_HB);
    __half* Wh1; cudaGetSymbolAddress((void**)&Wh1, g_Wh1);
    __half* Wh2; cudaGetSymbolAddress((void**)&Wh2, g_Wh2);
    __half* Wh3; cudaGetSymbolAddress((void**)&Wh3, g_Wh3);
    __half* Wh4; cudaGetSymbolAddress((void**)&Wh4, g_Wh4);

    // SMEM: A region (128*(K+8) halves) + 2 B buffers (2*9216 halves)
    const int SM128 = (128 * 136 + 2 * HTILE_HALVES) * 2;   // 71680 B
    const int SM256 = (128 * 264 + 2 * HTILE_HALVES) * 2;   // 104448 B
    cudaFuncSetAttribute(k_fused<128>,
                         cudaFuncAttributeMaxDynamicSharedMemorySize, SM128);
    cudaFuncSetAttribute(k_fused<256>,
                         cudaFuncAttributeMaxDynamicSharedMemorySize, SM256);

    const int nThreads = 256;
    int nBlkN = (NN + nThreads - 1) / nThreads;
    int nBlkE = (EE + nThreads - 1) / nThreads;
    int prepBlk = (int)((PREP_TOTAL + nThreads - 1) / nThreads);
    int fusedGrid = (NN + 127) / 128;

    k_prep<<<prepBlk, nThreads>>>(x, w1, w2, w3, w4, fc_w);
    k_hist<<<nBlkE, nThreads>>>(adj_row);
    k_scan1<<<NSCANBLK, SCAN_BLK>>>();
    k_scan2<<<1, 128>>>();
    k_scan3cur<<<nBlkN, nThreads>>>();
    k_scatter<<<nBlkE, nThreads>>>(adj_row, adj_col, adj_val);

    // Ping-pong buffers: input and output of each fused layer are DISTINCT.
    // Running scale: each gather multiplies stored values by 1/4 (sigma_l = 4^l).
    k_fused<128><<<fusedGrid, nThreads, SM128>>>(Xh, Wh1, b1, 1.f / 4.f, HA);
    k_fused<256><<<fusedGrid, nThreads, SM256>>>(HA, Wh2, b2, 1.f / 16.f, HB);
    k_fused<256><<<fusedGrid, nThreads, SM256>>>(HB, Wh3, b3, 1.f / 64.f, HA);
    k_fused<256><<<fusedGrid, nThreads, SM256>>>(HA, Wh4, b4, 1.f / 256.f, HB);

    int fcBlocks = (NN + 63) / 64;
    k_fc_hmma<<<fcBlocks, 128>>>(HB, fc_b, out);
}

// round 13
// speedup vs baseline: 1.3299x; 1.3299x over previous
#include <cuda_runtime.h>
#include <cuda_fp16.h>
#include <math.h>
#include <stdint.h>

#define NN 100000
#define EE 3200000
#define NHID 256
#define NCLASS 16
#define SCAN_BLK 1024
#define NSCANBLK ((NN + SCAN_BLK - 1) / SCAN_BLK)   // 98

// ---------------- scratch (static device globals) ---------------------------
__device__ __half g_Xh[(size_t)NN * 128];   // x in fp16
__device__ __half g_H[(size_t)NN * 256];    // layer activations, fp16 (scaled)
__device__ __half g_Agg[(size_t)NN * 256];  // SpMM output, fp16 (scaled)
__device__ int2   g_cv[EE];                 // packed (col, val) CSR payload
__device__ int    g_rowptr[NN + 1];
__device__ int    g_cursor[NN];
__device__ int    g_blocksums[SCAN_BLK];
__device__ __half g_Wh1[256 * 128];         // weights [n][k] K-major fp16
__device__ __half g_Wh2[256 * 256];
__device__ __half g_Wh3[256 * 256];
__device__ __half g_Wh4[256 * 256];
__device__ __half g_fwT[16 * 256];          // fc_w transposed [n][k] fp16

__device__ __forceinline__ uint32_t smem_u32(const void* p) {
    uint32_t a;
    asm("{ .reg .u64 t; cvta.to.shared.u64 t, %1; cvt.u32.u64 %0, t; }"
        : "=r"(a) : "l"(p));
    return a;
}

__device__ __forceinline__ void cpasync16(uint32_t dst, const void* src) {
    asm volatile("cp.async.ca.shared.global [%0], [%1], 16;" :: "r"(dst), "l"(src));
}

// ---------------- prep: fp16 conversions + cursor zero -----------------------
#define PREP_W1   (256 * 128)
#define PREP_W    (256 * 256)
#define PREP_FW   (16 * 256)
#define PREP_X4   ((long long)NN * 128 / 4)
#define PREP_TOTAL (PREP_W1 + 3LL * PREP_W + PREP_FW + PREP_X4 + NN)

__global__ void k_prep(const float* __restrict__ x,
                       const float* __restrict__ w1, const float* __restrict__ w2,
                       const float* __restrict__ w3, const float* __restrict__ w4,
                       const float* __restrict__ fcw) {
    long long i = (long long)blockIdx.x * blockDim.x + threadIdx.x;
    if (i < PREP_W1) {
        int n = (int)(i / 128), k = (int)(i % 128);
        g_Wh1[i] = __float2half_rn(w1[k * 256 + n]);
        return;
    }
    i -= PREP_W1;
    if (i < 3 * PREP_W) {
        int w = (int)(i / PREP_W);
        int r = (int)(i % PREP_W);
        int n = r / 256, k = r % 256;
        if (w == 0) g_Wh2[r] = __float2half_rn(w2[k * 256 + n]);
        else if (w == 1) g_Wh3[r] = __float2half_rn(w3[k * 256 + n]);
        else g_Wh4[r] = __float2half_rn(w4[k * 256 + n]);
        return;
    }
    i -= 3 * PREP_W;
    if (i < PREP_FW) {
        int n = (int)(i / 256), k = (int)(i % 256);
        g_fwT[i] = __float2half_rn(fcw[k * 16 + n]);
        return;
    }
    i -= PREP_FW;
    if (i < PREP_X4) {
        float4 v = ((const float4*)x)[i];
        __half2 h0 = __floats2half2_rn(v.x, v.y);
        __half2 h1 = __floats2half2_rn(v.z, v.w);
        ((uint2*)g_Xh)[i] = make_uint2(*(uint32_t*)&h0, *(uint32_t*)&h1);
        return;
    }
    i -= PREP_X4;
    if (i < NN) g_cursor[i] = 0;
}

// ---------------- CSR build --------------------------------------------------
__global__ void k_hist(const int* __restrict__ row) {
    int e = blockIdx.x * blockDim.x + threadIdx.x;
    if (e < EE) atomicAdd(&g_cursor[row[e]], 1);
}

__global__ void k_scan1() {
    __shared__ int s[SCAN_BLK];
    int t = threadIdx.x;
    int gid = blockIdx.x * SCAN_BLK + t;
    s[t] = (gid < NN) ? g_cursor[gid] : 0;
    for (int d = 1; d < SCAN_BLK; d <<= 1) {
        __syncthreads();
        int u = (t >= d) ? s[t - d] : 0;
        __syncthreads();
        s[t] += u;
    }
    __syncthreads();
    if (gid < NN) g_rowptr[gid + 1] = s[t];
    if (t == SCAN_BLK - 1) g_blocksums[blockIdx.x] = s[t];
}

__global__ void k_scan2() {
    __shared__ int s[128];
    int t = threadIdx.x;
    s[t] = (t < NSCANBLK) ? g_blocksums[t] : 0;
    for (int d = 1; d < 128; d <<= 1) {
        __syncthreads();
        int u = (t >= d) ? s[t - d] : 0;
        __syncthreads();
        s[t] += u;
    }
    __syncthreads();
    if (t < NSCANBLK) g_blocksums[t] = s[t];
}

__global__ void k_scan3cur() {
    int i = blockIdx.x * blockDim.x + threadIdx.x;
    if (i < NN) {
        int b = i >> 10;
        int off = b ? g_blocksums[b - 1] : 0;
        int v = g_rowptr[i + 1] + off;
        g_rowptr[i + 1] = v;
        if (i + 1 < NN) g_cursor[i + 1] = v;
        if (i == 0) { g_rowptr[0] = 0; g_cursor[0] = 0; }
    }
}

__global__ void k_scatter(const int* __restrict__ row, const int* __restrict__ col,
                          const float* __restrict__ val) {
    int e = blockIdx.x * blockDim.x + threadIdx.x;
    if (e < EE) {
        int r = row[e];
        int p = atomicAdd(&g_cursor[r], 1);
        g_cv[p] = make_int2(col[e], __float_as_int(val[e]));
    }
}

// ---------------- SpMM (CSR, fp16 gather -> fp16 out, scaled by 1/4) --------
// One warp per dest node. NC = 128 (layer 1) or 256. (R8/R10-proven version)
template <int NC>
__global__ void k_spmm(const __half* __restrict__ S, __half* __restrict__ out) {
    int w = (blockIdx.x * blockDim.x + threadIdx.x) >> 5;
    if (w >= NN) return;
    int lane = threadIdx.x & 31;
    constexpr int HP = NC / 32;

    float acc[HP];
#pragma unroll
    for (int i = 0; i < HP; i++) acc[i] = 0.f;

    int s = g_rowptr[w], e = g_rowptr[w + 1];
    for (int base = s; base < e; base += 32) {
        int idx = base + lane;
        int c = 0;
        float v = 0.f;
        if (idx < e) {
            int2 q = g_cv[idx];
            c = q.x;
            v = __int_as_float(q.y);
        }
        int m = min(32, e - base);
#pragma unroll 8
        for (int j = 0; j < 32; j++) {
            if (j >= m) break;
            int cj = __shfl_sync(0xffffffffu, c, j);
            float vj = __shfl_sync(0xffffffffu, v, j);
            if (NC == 256) {
                uint4 q = ((const uint4*)S)[(size_t)cj * 32 + lane];
                const __half2* h = (const __half2*)&q;
#pragma unroll
                for (int p = 0; p < 4; p++) {
                    float2 f = __half22float2(h[p]);
                    acc[p * 2] += vj * f.x;
                    acc[p * 2 + 1] += vj * f.y;
                }
            } else {
                uint2 q = ((const uint2*)S)[(size_t)cj * 32 + lane];
                const __half2* h = (const __half2*)&q;
#pragma unroll
                for (int p = 0; p < 2; p++) {
                    float2 f = __half22float2(h[p]);
                    acc[p * 2] += vj * f.x;
                    acc[p * 2 + 1] += vj * f.y;
                }
            }
        }
    }
    const float SC = 0.25f;
    __half2 o[HP / 2];
#pragma unroll
    for (int p = 0; p < HP / 2; p++)
        o[p] = __floats2half2_rn(acc[p * 2] * SC, acc[p * 2 + 1] * SC);
    if (NC == 256)
        ((uint4*)out)[(size_t)w * 32 + lane] = *(uint4*)o;
    else
        ((uint2*)out)[(size_t)w * 32 + lane] = *(uint2*)o;
}

// ---------------- fp16 HMMA GEMM + fused (scaled) bias + relu (R8 version) ---
#define HBK 64
#define HROW 72                        // +8 halves pad (16B)
#define HTILE_HALVES (128 * HROW)      // 9216 halves = 18432 B per tile

__global__ void __launch_bounds__(256, 2) k_gemm_h(
    const __half* __restrict__ A, const __half* __restrict__ Wt,
    const float* __restrict__ bias, float bscale,
    __half* __restrict__ C, int M, int K) {
    extern __shared__ __half sm[];
    uint32_t sb = smem_u32(sm);
    int tid = threadIdx.x;
    int wid = tid >> 5, lane = tid & 31;
    int wm = wid & 1, wn = wid >> 1;
    int gid = lane >> 2, tg = lane & 3;

    int row0 = blockIdx.x * 128;
    int col0 = blockIdx.y * 128;
    int nIter = K / HBK;

    const int aoff[2] = {0, 2 * HTILE_HALVES};
    const int boff[2] = {HTILE_HALVES, 3 * HTILE_HALVES};

    float acc[4][4][4];
#pragma unroll
    for (int i = 0; i < 4; i++)
#pragma unroll
        for (int j = 0; j < 4; j++)
#pragma unroll
            for (int k = 0; k < 4; k++) acc[i][j][k] = 0.f;

    auto stage = [&](int c, int buf) {
        int k0 = c * HBK;
        const __half* Ag = A + (size_t)row0 * K + k0;
#pragma unroll
        for (int it = 0; it < 4; it++) {
            int idx = tid + it * 256;
            int r = idx >> 3, c8 = idx & 7;
            if (row0 + r < M)
                cpasync16(sb + (uint32_t)(aoff[buf] + r * HROW) * 2 + c8 * 16,
                          Ag + (size_t)r * K + c8 * 8);
        }
        const __half* Bg = Wt + (size_t)col0 * K + k0;
#pragma unroll
        for (int it = 0; it < 4; it++) {
            int idx = tid + it * 256;
            int r = idx >> 3, c8 = idx & 7;
            cpasync16(sb + (uint32_t)(boff[buf] + r * HROW) * 2 + c8 * 16,
                      Bg + (size_t)r * K + c8 * 8);
        }
        asm volatile("cp.async.commit_group;" ::: "memory");
    };

    stage(0, 0);

    for (int c = 0; c < nIter; c++) {
        int buf = c & 1;
        if (c + 1 < nIter) {
            stage(c + 1, buf ^ 1);
            asm volatile("cp.async.wait_group 1;" ::: "memory");
        } else {
            asm volatile("cp.async.wait_group 0;" ::: "memory");
        }
        __syncthreads();

        const uint32_t* As = (const uint32_t*)(sm + aoff[buf]);
        const uint32_t* Bs = (const uint32_t*)(sm + boff[buf]);

#pragma unroll
        for (int ks = 0; ks < 4; ks++) {
            int k = ks * 16;
            uint32_t a[4][4], b[4][2];
#pragma unroll
            for (int mt = 0; mt < 4; mt++) {
                int rb = wm * 64 + mt * 16 + gid;
                int base0 = (rb * HROW + k) >> 1;
                int base1 = ((rb + 8) * HROW + k) >> 1;
                a[mt][0] = As[base0 + tg];
                a[mt][1] = As[base1 + tg];
                a[mt][2] = As[base0 + tg + 4];
                a[mt][3] = As[base1 + tg + 4];
            }
#pragma unroll
            for (int nt = 0; nt < 4; nt++) {
                int nb = wn * 32 + nt * 8 + gid;
                int base = (nb * HROW + k) >> 1;
                b[nt][0] = Bs[base + tg];
                b[nt][1] = Bs[base + tg + 4];
            }
#pragma unroll
            for (int mt = 0; mt < 4; mt++)
#pragma unroll
                for (int nt = 0; nt < 4; nt++) {
                    float* d = acc[mt][nt];
                    asm volatile(
                        "mma.sync.aligned.m16n8k16.row.col.f32.f16.f16.f32 "
                        "{%0,%1,%2,%3}, {%4,%5,%6,%7}, {%8,%9}, {%0,%1,%2,%3};"
                        : "+f"(d[0]), "+f"(d[1]), "+f"(d[2]), "+f"(d[3])
                        : "r"(a[mt][0]), "r"(a[mt][1]), "r"(a[mt][2]), "r"(a[mt][3]),
                          "r"(b[nt][0]), "r"(b[nt][1]));
                }
        }
        __syncthreads();
    }

#pragma unroll
    for (int nt = 0; nt < 4; nt++) {
        int cg = col0 + wn * 32 + nt * 8 + tg * 2;
        float bx = bias[cg] * bscale, by = bias[cg + 1] * bscale;
#pragma unroll
        for (int mt = 0; mt < 4; mt++) {
            int rg = row0 + wm * 64 + mt * 16 + gid;
            float* d = acc[mt][nt];
            if (rg < M) {
                float v0 = fmaxf(d[0] + bx, 0.f);
                float v1 = fmaxf(d[1] + by, 0.f);
                *(__half2*)(C + (size_t)rg * 256 + cg) = __floats2half2_rn(v0, v1);
            }
            if (rg + 8 < M) {
                float v2 = fmaxf(d[2] + bx, 0.f);
                float v3 = fmaxf(d[3] + by, 0.f);
                *(__half2*)(C + (size_t)(rg + 8) * 256 + cg) = __floats2half2_rn(v2, v3);
            }
        }
    }
}

// ---------------- HMMA FC + log_softmax (fp16 H at scale 1/256) --------------
__global__ void __launch_bounds__(128) k_fc_hmma(const __half* __restrict__ H,
                                                 const float* __restrict__ fb,
                                                 float* __restrict__ out) {
    __shared__ float sfb[16];
    int tid = threadIdx.x;
    if (tid < 16) sfb[tid] = fb[tid];
    __syncthreads();

    int wid = tid >> 5, lane = tid & 31;
    int gid = lane >> 2, tg = lane & 3;
    int row0 = (blockIdx.x * 4 + wid) * 16;
    if (row0 >= NN) return;

    int rA = row0 + gid;
    int rB = row0 + gid + 8;
    int rAc = min(rA, NN - 1);
    int rBc = min(rB, NN - 1);

    float c0[4] = {0.f, 0.f, 0.f, 0.f};
    float c1[4] = {0.f, 0.f, 0.f, 0.f};

    const __half* HA = H + (size_t)rAc * 256;
    const __half* HB = H + (size_t)rBc * 256;
    const __half* W0 = g_fwT + (size_t)gid * 256;
    const __half* W1 = g_fwT + (size_t)(gid + 8) * 256;

#pragma unroll
    for (int kc = 0; kc < 16; kc++) {
        int k = kc * 16;
        uint32_t a0 = *(const uint32_t*)(HA + k + 2 * tg);
        uint32_t a1 = *(const uint32_t*)(HB + k + 2 * tg);
        uint32_t a2 = *(const uint32_t*)(HA + k + 2 * tg + 8);
        uint32_t a3 = *(const uint32_t*)(HB + k + 2 * tg + 8);
        uint32_t b00 = *(const uint32_t*)(W0 + k + 2 * tg);
        uint32_t b01 = *(const uint32_t*)(W0 + k + 2 * tg + 8);
        uint32_t b10 = *(const uint32_t*)(W1 + k + 2 * tg);
        uint32_t b11 = *(const uint32_t*)(W1 + k + 2 * tg + 8);
        asm volatile(
            "mma.sync.aligned.m16n8k16.row.col.f32.f16.f16.f32 "
            "{%0,%1,%2,%3}, {%4,%5,%6,%7}, {%8,%9}, {%0,%1,%2,%3};"
            : "+f"(c0[0]), "+f"(c0[1]), "+f"(c0[2]), "+f"(c0[3])
            : "r"(a0), "r"(a1), "r"(a2), "r"(a3), "r"(b00), "r"(b01));
        asm volatile(
            "mma.sync.aligned.m16n8k16.row.col.f32.f16.f16.f32 "
            "{%0,%1,%2,%3}, {%4,%5,%6,%7}, {%8,%9}, {%0,%1,%2,%3};"
            : "+f"(c1[0]), "+f"(c1[1]), "+f"(c1[2]), "+f"(c1[3])
            : "r"(a0), "r"(a1), "r"(a2), "r"(a3), "r"(b10), "r"(b11));
    }

    float fb0 = sfb[2 * tg], fb1 = sfb[2 * tg + 1];
    float fb2 = sfb[8 + 2 * tg], fb3 = sfb[8 + 2 * tg + 1];

#pragma unroll
    for (int rr = 0; rr < 2; rr++) {
        int row = rr ? rB : rA;
        float v0 = (rr ? c0[2] : c0[0]) * 256.f + fb0;
        float v1 = (rr ? c0[3] : c0[1]) * 256.f + fb1;
        float v2 = (rr ? c1[2] : c1[0]) * 256.f + fb2;
        float v3 = (rr ? c1[3] : c1[1]) * 256.f + fb3;
        float mx = fmaxf(fmaxf(v0, v1), fmaxf(v2, v3));
        mx = fmaxf(mx, __shfl_xor_sync(0xffffffffu, mx, 1));
        mx = fmaxf(mx, __shfl_xor_sync(0xffffffffu, mx, 2));
        float sm = expf(v0 - mx) + expf(v1 - mx) + expf(v2 - mx) + expf(v3 - mx);
        sm += __shfl_xor_sync(0xffffffffu, sm, 1);
        sm += __shfl_xor_sync(0xffffffffu, sm, 2);
        float ls = logf(sm);
        if (row < NN) {
            float* o = out + (size_t)row * 16;
            *(float2*)(o + 2 * tg) = make_float2((v0 - mx) - ls, (v1 - mx) - ls);
            *(float2*)(o + 8 + 2 * tg) = make_float2((v2 - mx) - ls, (v3 - mx) - ls);
        }
    }
}

// ---------------- launch -----------------------------------------------------
extern "C" void kernel_launch(void* const* d_in, const int* in_sizes, int n_in,
                              void* d_out, int out_size) {
    const float* x    = (const float*)d_in[0];
    const float* adj_val = (const float*)d_in[1];
    const float* w1 = (const float*)d_in[2];
    const float* b1 = (const float*)d_in[3];
    const float* w2 = (const float*)d_in[4];
    const float* b2 = (const float*)d_in[5];
    const float* w3 = (const float*)d_in[6];
    const float* b3 = (const float*)d_in[7];
    const float* w4 = (const float*)d_in[8];
    const float* b4 = (const float*)d_in[9];
    const float* fc_w = (const float*)d_in[10];
    const float* fc_b = (const float*)d_in[11];
    const int* adj_row = (const int*)d_in[12];
    const int* adj_col = (const int*)d_in[13];
    float* out = (float*)d_out;

    __half* Xh;  cudaGetSymbolAddress((void**)&Xh, g_Xh);
    __half* H;   cudaGetSymbolAddress((void**)&H, g_H);
    __half* Agg; cudaGetSymbolAddress((void**)&Agg, g_Agg);
    __half* Wh1; cudaGetSymbolAddress((void**)&Wh1, g_Wh1);
    __half* Wh2; cudaGetSymbolAddress((void**)&Wh2, g_Wh2);
    __half* Wh3; cudaGetSymbolAddress((void**)&Wh3, g_Wh3);
    __half* Wh4; cudaGetSymbolAddress((void**)&Wh4, g_Wh4);

    const int GSMEM = 4 * HTILE_HALVES * 2;   // 73728 bytes
    cudaFuncSetAttribute(k_gemm_h, cudaFuncAttributeMaxDynamicSharedMemorySize, GSMEM);

    const int nThreads = 256;
    int nBlkN = (NN + nThreads - 1) / nThreads;
    int nBlkE = (EE + nThreads - 1) / nThreads;
    int prepBlk = (int)((PREP_TOTAL + nThreads - 1) / nThreads);

    dim3 gemmGrid((NN + 127) / 128, 2);
    int spmmBlocks = (NN * 32 + nThreads - 1) / nThreads;

    k_prep<<<prepBlk, nThreads>>>(x, w1, w2, w3, w4, fc_w);
    k_hist<<<nBlkE, nThreads>>>(adj_row);
    k_scan1<<<NSCANBLK, SCAN_BLK>>>();
    k_scan2<<<1, 128>>>();
    k_scan3cur<<<nBlkN, nThreads>>>();
    k_scatter<<<nBlkE, nThreads>>>(adj_row, adj_col, adj_val);

    // Running scale: each spmm multiplies stored values by 1/4 (sigma_l = 4^l).
    k_spmm<128><<<spmmBlocks, nThreads>>>(Xh, Agg);
    k_gemm_h<<<gemmGrid, nThreads, GSMEM>>>(Agg, Wh1, b1, 1.f / 4.f, H, NN, 128);
    k_spmm<256><<<spmmBlocks, nThreads>>>(H, Agg);
    k_gemm_h<<<gemmGrid, nThreads, GSMEM>>>(Agg, Wh2, b2, 1.f / 16.f, H, NN, 256);
    k_spmm<256><<<spmmBlocks, nThreads>>>(H, Agg);
    k_gemm_h<<<gemmGrid, nThreads, GSMEM>>>(Agg, Wh3, b3, 1.f / 64.f, H, NN, 256);
    k_spmm<256><<<spmmBlocks, nThreads>>>(H, Agg);
    k_gemm_h<<<gemmGrid, nThreads, GSMEM>>>(Agg, Wh4, b4, 1.f / 256.f, H, NN, 256);

    int fcBlocks = (NN + 63) / 64;
    k_fc_hmma<<<fcBlocks, 128>>>(H, fc_b, out);
}

// round 14
// speedup vs baseline: 1.3373x; 1.0055x over previous
#include <cuda_runtime.h>
#include <cuda_fp16.h>
#include <math.h>
#include <stdint.h>

#define NN 100000
#define EE 3200000
#define NHID 256
#define NCLASS 16
#define SCAN_BLK 1024
#define NSCANBLK ((NN + SCAN_BLK - 1) / SCAN_BLK)   // 98

// ---------------- scratch (static device globals) ---------------------------
__device__ __half g_Xh[(size_t)NN * 128];   // x in fp16
__device__ __half g_H[(size_t)NN * 256];    // layer activations, fp16 (scaled)
__device__ __half g_Agg[(size_t)NN * 256];  // SpMM output, fp16 (scaled)
__device__ int2   g_cv[EE];                 // packed (col, val) CSR payload
__device__ int    g_rowptr[NN + 1];
__device__ int    g_cursor[NN];
__device__ int    g_blocksums[SCAN_BLK];
__device__ __half g_Wh1[256 * 128];         // weights [n][k] K-major fp16
__device__ __half g_Wh2[256 * 256];
__device__ __half g_Wh3[256 * 256];
__device__ __half g_Wh4[256 * 256];
__device__ __half g_fwT[16 * 256];          // fc_w transposed [n][k] fp16

__device__ __forceinline__ uint32_t smem_u32(const void* p) {
    uint32_t a;
    asm("{ .reg .u64 t; cvta.to.shared.u64 t, %1; cvt.u32.u64 %0, t; }"
        : "=r"(a) : "l"(p));
    return a;
}

__device__ __forceinline__ void cpasync16(uint32_t dst, const void* src) {
    asm volatile("cp.async.ca.shared.global [%0], [%1], 16;" :: "r"(dst), "l"(src));
}

// L2-only (bypass L1) vector loads for the streaming gather
__device__ __forceinline__ uint4 ldg_cg_v4(const void* p) {
    uint4 q;
    asm volatile("ld.global.cg.v4.b32 {%0,%1,%2,%3}, [%4];"
                 : "=r"(q.x), "=r"(q.y), "=r"(q.z), "=r"(q.w) : "l"(p));
    return q;
}
__device__ __forceinline__ uint2 ldg_cg_v2(const void* p) {
    uint2 q;
    asm volatile("ld.global.cg.v2.b32 {%0,%1}, [%2];"
                 : "=r"(q.x), "=r"(q.y) : "l"(p));
    return q;
}

// ---------------- prep: fp16 conversions + cursor zero -----------------------
#define PREP_W1   (256 * 128)
#define PREP_W    (256 * 256)
#define PREP_FW   (16 * 256)
#define PREP_X4   ((long long)NN * 128 / 4)
#define PREP_TOTAL (PREP_W1 + 3LL * PREP_W + PREP_FW + PREP_X4 + NN)

__global__ void k_prep(const float* __restrict__ x,
                       const float* __restrict__ w1, const float* __restrict__ w2,
                       const float* __restrict__ w3, const float* __restrict__ w4,
                       const float* __restrict__ fcw) {
    long long i = (long long)blockIdx.x * blockDim.x + threadIdx.x;
    if (i < PREP_W1) {
        int n = (int)(i / 128), k = (int)(i % 128);
        g_Wh1[i] = __float2half_rn(w1[k * 256 + n]);
        return;
    }
    i -= PREP_W1;
    if (i < 3 * PREP_W) {
        int w = (int)(i / PREP_W);
        int r = (int)(i % PREP_W);
        int n = r / 256, k = r % 256;
        if (w == 0) g_Wh2[r] = __float2half_rn(w2[k * 256 + n]);
        else if (w == 1) g_Wh3[r] = __float2half_rn(w3[k * 256 + n]);
        else g_Wh4[r] = __float2half_rn(w4[k * 256 + n]);
        return;
    }
    i -= 3 * PREP_W;
    if (i < PREP_FW) {
        int n = (int)(i / 256), k = (int)(i % 256);
        g_fwT[i] = __float2half_rn(fcw[k * 16 + n]);
        return;
    }
    i -= PREP_FW;
    if (i < PREP_X4) {
        float4 v = ((const float4*)x)[i];
        __half2 h0 = __floats2half2_rn(v.x, v.y);
        __half2 h1 = __floats2half2_rn(v.z, v.w);
        ((uint2*)g_Xh)[i] = make_uint2(*(uint32_t*)&h0, *(uint32_t*)&h1);
        return;
    }
    i -= PREP_X4;
    if (i < NN) g_cursor[i] = 0;
}

// ---------------- CSR build --------------------------------------------------
__global__ void k_hist(const int* __restrict__ row) {
    int e = blockIdx.x * blockDim.x + threadIdx.x;
    if (e < EE) atomicAdd(&g_cursor[row[e]], 1);
}

__global__ void k_scan1() {
    __shared__ int s[SCAN_BLK];
    int t = threadIdx.x;
    int gid = blockIdx.x * SCAN_BLK + t;
    s[t] = (gid < NN) ? g_cursor[gid] : 0;
    for (int d = 1; d < SCAN_BLK; d <<= 1) {
        __syncthreads();
        int u = (t >= d) ? s[t - d] : 0;
        __syncthreads();
        s[t] += u;
    }
    __syncthreads();
    if (gid < NN) g_rowptr[gid + 1] = s[t];
    if (t == SCAN_BLK - 1) g_blocksums[blockIdx.x] = s[t];
}

__global__ void k_scan2() {
    __shared__ int s[128];
    int t = threadIdx.x;
    s[t] = (t < NSCANBLK) ? g_blocksums[t] : 0;
    for (int d = 1; d < 128; d <<= 1) {
        __syncthreads();
        int u = (t >= d) ? s[t - d] : 0;
        __syncthreads();
        s[t] += u;
    }
    __syncthreads();
    if (t < NSCANBLK) g_blocksums[t] = s[t];
}

__global__ void k_scan3cur() {
    int i = blockIdx.x * blockDim.x + threadIdx.x;
    if (i < NN) {
        int b = i >> 10;
        int off = b ? g_blocksums[b - 1] : 0;
        int v = g_rowptr[i + 1] + off;
        g_rowptr[i + 1] = v;
        if (i + 1 < NN) g_cursor[i + 1] = v;
        if (i == 0) { g_rowptr[0] = 0; g_cursor[0] = 0; }
    }
}

__global__ void k_scatter(const int* __restrict__ row, const int* __restrict__ col,
                          const float* __restrict__ val) {
    int e = blockIdx.x * blockDim.x + threadIdx.x;
    if (e < EE) {
        int r = row[e];
        int p = atomicAdd(&g_cursor[r], 1);
        g_cv[p] = make_int2(col[e], __float_as_int(val[e]));
    }
}

// ---------------- SpMM (CSR, fp16 gather -> fp16 out, scaled by 1/4) --------
// One warp per dest node. Branchless cv load; gather bypasses L1 (.cg).
template <int NC>
__global__ void k_spmm(const __half* __restrict__ S, __half* __restrict__ out) {
    int w = (blockIdx.x * blockDim.x + threadIdx.x) >> 5;
    if (w >= NN) return;
    int lane = threadIdx.x & 31;
    constexpr int HP = NC / 32;

    float acc[HP];
#pragma unroll
    for (int i = 0; i < HP; i++) acc[i] = 0.f;

    int s = g_rowptr[w], e = g_rowptr[w + 1];
    for (int base = s; base < e; base += 32) {
        int idx = base + lane;
        int idxc = min(idx, e - 1);          // branchless clamped load
        int2 q0 = g_cv[idxc];
        int c = q0.x;
        float v = (idx < e) ? __int_as_float(q0.y) : 0.f;
        int m = min(32, e - base);
#pragma unroll 8
        for (int j = 0; j < 32; j++) {
            if (j >= m) break;
            int cj = __shfl_sync(0xffffffffu, c, j);
            float vj = __shfl_sync(0xffffffffu, v, j);
            if (NC == 256) {
                uint4 q = ldg_cg_v4((const uint4*)S + (size_t)cj * 32 + lane);
                const __half2* h = (const __half2*)&q;
#pragma unroll
                for (int p = 0; p < 4; p++) {
                    float2 f = __half22float2(h[p]);
                    acc[p * 2] += vj * f.x;
                    acc[p * 2 + 1] += vj * f.y;
                }
            } else {
                uint2 q = ldg_cg_v2((const uint2*)S + (size_t)cj * 32 + lane);
                const __half2* h = (const __half2*)&q;
#pragma unroll
                for (int p = 0; p < 2; p++) {
                    float2 f = __half22float2(h[p]);
                    acc[p * 2] += vj * f.x;
                    acc[p * 2 + 1] += vj * f.y;
                }
            }
        }
    }
    const float SC = 0.25f;
    __half2 o[HP / 2];
#pragma unroll
    for (int p = 0; p < HP / 2; p++)
        o[p] = __floats2half2_rn(acc[p * 2] * SC, acc[p * 2 + 1] * SC);
    if (NC == 256)
        ((uint4*)out)[(size_t)w * 32 + lane] = *(uint4*)o;
    else
        ((uint2*)out)[(size_t)w * 32 + lane] = *(uint2*)o;
}

// ---------------- fp16 HMMA GEMM + fused (scaled) bias + relu (R8 version) ---
#define HBK 64
#define HROW 72                        // +8 halves pad (16B)
#define HTILE_HALVES (128 * HROW)      // 9216 halves = 18432 B per tile

__global__ void __launch_bounds__(256, 2) k_gemm_h(
    const __half* __restrict__ A, const __half* __restrict__ Wt,
    const float* __restrict__ bias, float bscale,
    __half* __restrict__ C, int M, int K) {
    extern __shared__ __half sm[];
    uint32_t sb = smem_u32(sm);
    int tid = threadIdx.x;
    int wid = tid >> 5, lane = tid & 31;
    int wm = wid & 1, wn = wid >> 1;
    int gid = lane >> 2, tg = lane & 3;

    int row0 = blockIdx.x * 128;
    int col0 = blockIdx.y * 128;
    int nIter = K / HBK;

    const int aoff[2] = {0, 2 * HTILE_HALVES};
    const int boff[2] = {HTILE_HALVES, 3 * HTILE_HALVES};

    float acc[4][4][4];
#pragma unroll
    for (int i = 0; i < 4; i++)
#pragma unroll
        for (int j = 0; j < 4; j++)
#pragma unroll
            for (int k = 0; k < 4; k++) acc[i][j][k] = 0.f;

    auto stage = [&](int c, int buf) {
        int k0 = c * HBK;
        const __half* Ag = A + (size_t)row0 * K + k0;
#pragma unroll
        for (int it = 0; it < 4; it++) {
            int idx = tid + it * 256;
            int r = idx >> 3, c8 = idx & 7;
            if (row0 + r < M)
                cpasync16(sb + (uint32_t)(aoff[buf] + r * HROW) * 2 + c8 * 16,
                          Ag + (size_t)r * K + c8 * 8);
        }
        const __half* Bg = Wt + (size_t)col0 * K + k0;
#pragma unroll
        for (int it = 0; it < 4; it++) {
            int idx = tid + it * 256;
            int r = idx >> 3, c8 = idx & 7;
            cpasync16(sb + (uint32_t)(boff[buf] + r * HROW) * 2 + c8 * 16,
                      Bg + (size_t)r * K + c8 * 8);
        }
        asm volatile("cp.async.commit_group;" ::: "memory");
    };

    stage(0, 0);

    for (int c = 0; c < nIter; c++) {
        int buf = c & 1;
        if (c + 1 < nIter) {
            stage(c + 1, buf ^ 1);
            asm volatile("cp.async.wait_group 1;" ::: "memory");
        } else {
            asm volatile("cp.async.wait_group 0;" ::: "memory");
        }
        __syncthreads();

        const uint32_t* As = (const uint32_t*)(sm + aoff[buf]);
        const uint32_t* Bs = (const uint32_t*)(sm + boff[buf]);

#pragma unroll
        for (int ks = 0; ks < 4; ks++) {
            int k = ks * 16;
            uint32_t a[4][4], b[4][2];
#pragma unroll
            for (int mt = 0; mt < 4; mt++) {
                int rb = wm * 64 + mt * 16 + gid;
                int base0 = (rb * HROW + k) >> 1;
                int base1 = ((rb + 8) * HROW + k) >> 1;
                a[mt][0] = As[base0 + tg];
                a[mt][1] = As[base1 + tg];
                a[mt][2] = As[base0 + tg + 4];
                a[mt][3] = As[base1 + tg + 4];
            }
#pragma unroll
            for (int nt = 0; nt < 4; nt++) {
                int nb = wn * 32 + nt * 8 + gid;
                int base = (nb * HROW + k) >> 1;
                b[nt][0] = Bs[base + tg];
                b[nt][1] = Bs[base + tg + 4];
            }
#pragma unroll
            for (int mt = 0; mt < 4; mt++)
#pragma unroll
                for (int nt = 0; nt < 4; nt++) {
                    float* d = acc[mt][nt];
                    asm volatile(
                        "mma.sync.aligned.m16n8k16.row.col.f32.f16.f16.f32 "
                        "{%0,%1,%2,%3}, {%4,%5,%6,%7}, {%8,%9}, {%0,%1,%2,%3};"
                        : "+f"(d[0]), "+f"(d[1]), "+f"(d[2]), "+f"(d[3])
                        : "r"(a[mt][0]), "r"(a[mt][1]), "r"(a[mt][2]), "r"(a[mt][3]),
                          "r"(b[nt][0]), "r"(b[nt][1]));
                }
        }
        __syncthreads();
    }

#pragma unroll
    for (int nt = 0; nt < 4; nt++) {
        int cg = col0 + wn * 32 + nt * 8 + tg * 2;
        float bx = bias[cg] * bscale, by = bias[cg + 1] * bscale;
#pragma unroll
        for (int mt = 0; mt < 4; mt++) {
            int rg = row0 + wm * 64 + mt * 16 + gid;
            float* d = acc[mt][nt];
            if (rg < M) {
                float v0 = fmaxf(d[0] + bx, 0.f);
                float v1 = fmaxf(d[1] + by, 0.f);
                *(__half2*)(C + (size_t)rg * 256 + cg) = __floats2half2_rn(v0, v1);
            }
            if (rg + 8 < M) {
                float v2 = fmaxf(d[2] + bx, 0.f);
                float v3 = fmaxf(d[3] + by, 0.f);
                *(__half2*)(C + (size_t)(rg + 8) * 256 + cg) = __floats2half2_rn(v2, v3);
            }
        }
    }
}

// ---------------- HMMA FC + log_softmax (fp16 H at scale 1/256) --------------
__global__ void __launch_bounds__(128) k_fc_hmma(const __half* __restrict__ H,
                                                 const float* __restrict__ fb,
                                                 float* __restrict__ out) {
    __shared__ float sfb[16];
    int tid = threadIdx.x;
    if (tid < 16) sfb[tid] = fb[tid];
    __syncthreads();

    int wid = tid >> 5, lane = tid & 31;
    int gid = lane >> 2, tg = lane & 3;
    int row0 = (blockIdx.x * 4 + wid) * 16;
    if (row0 >= NN) return;

    int rA = row0 + gid;
    int rB = row0 + gid + 8;
    int rAc = min(rA, NN - 1);
    int rBc = min(rB, NN - 1);

    float c0[4] = {0.f, 0.f, 0.f, 0.f};
    float c1[4] = {0.f, 0.f, 0.f, 0.f};

    const __half* HA = H + (size_t)rAc * 256;
    const __half* HB = H + (size_t)rBc * 256;
    const __half* W0 = g_fwT + (size_t)gid * 256;
    const __half* W1 = g_fwT + (size_t)(gid + 8) * 256;

#pragma unroll
    for (int kc = 0; kc < 16; kc++) {
        int k = kc * 16;
        uint32_t a0 = *(const uint32_t*)(HA + k + 2 * tg);
        uint32_t a1 = *(const uint32_t*)(HB + k + 2 * tg);
        uint32_t a2 = *(const uint32_t*)(HA + k + 2 * tg + 8);
        uint32_t a3 = *(const uint32_t*)(HB + k + 2 * tg + 8);
        uint32_t b00 = *(const uint32_t*)(W0 + k + 2 * tg);
        uint32_t b01 = *(const uint32_t*)(W0 + k + 2 * tg + 8);
        uint32_t b10 = *(const uint32_t*)(W1 + k + 2 * tg);
        uint32_t b11 = *(const uint32_t*)(W1 + k + 2 * tg + 8);
        asm volatile(
            "mma.sync.aligned.m16n8k16.row.col.f32.f16.f16.f32 "
            "{%0,%1,%2,%3}, {%4,%5,%6,%7}, {%8,%9}, {%0,%1,%2,%3};"
            : "+f"(c0[0]), "+f"(c0[1]), "+f"(c0[2]), "+f"(c0[3])
            : "r"(a0), "r"(a1), "r"(a2), "r"(a3), "r"(b00), "r"(b01));
        asm volatile(
            "mma.sync.aligned.m16n8k16.row.col.f32.f16.f16.f32 "
            "{%0,%1,%2,%3}, {%4,%5,%6,%7}, {%8,%9}, {%0,%1,%2,%3};"
            : "+f"(c1[0]), "+f"(c1[1]), "+f"(c1[2]), "+f"(c1[3])
            : "r"(a0), "r"(a1), "r"(a2), "r"(a3), "r"(b10), "r"(b11));
    }

    float fb0 = sfb[2 * tg], fb1 = sfb[2 * tg + 1];
    float fb2 = sfb[8 + 2 * tg], fb3 = sfb[8 + 2 * tg + 1];

#pragma unroll
    for (int rr = 0; rr < 2; rr++) {
        int row = rr ? rB : rA;
        float v0 = (rr ? c0[2] : c0[0]) * 256.f + fb0;
        float v1 = (rr ? c0[3] : c0[1]) * 256.f + fb1;
        float v2 = (rr ? c1[2] : c1[0]) * 256.f + fb2;
        float v3 = (rr ? c1[3] : c1[1]) * 256.f + fb3;
        float mx = fmaxf(fmaxf(v0, v1), fmaxf(v2, v3));
        mx = fmaxf(mx, __shfl_xor_sync(0xffffffffu, mx, 1));
        mx = fmaxf(mx, __shfl_xor_sync(0xffffffffu, mx, 2));
        float sm = expf(v0 - mx) + expf(v1 - mx) + expf(v2 - mx) + expf(v3 - mx);
        sm += __shfl_xor_sync(0xffffffffu, sm, 1);
        sm += __shfl_xor_sync(0xffffffffu, sm, 2);
        float ls = logf(sm);
        if (row < NN) {
            float* o = out + (size_t)row * 16;
            *(float2*)(o + 2 * tg) = make_float2((v0 - mx) - ls, (v1 - mx) - ls);
            *(float2*)(o + 8 + 2 * tg) = make_float2((v2 - mx) - ls, (v3 - mx) - ls);
        }
    }
}

// ---------------- launch -----------------------------------------------------
extern "C" void kernel_launch(void* const* d_in, const int* in_sizes, int n_in,
                              void* d_out, int out_size) {
    const float* x    = (const float*)d_in[0];
    const float* adj_val = (const float*)d_in[1];
    const float* w1 = (const float*)d_in[2];
    const float* b1 = (const float*)d_in[3];
    const float* w2 = (const float*)d_in[4];
    const float* b2 = (const float*)d_in[5];
    const float* w3 = (const float*)d_in[6];
    const float* b3 = (const float*)d_in[7];
    const float* w4 = (const float*)d_in[8];
    const float* b4 = (const float*)d_in[9];
    const float* fc_w = (const float*)d_in[10];
    const float* fc_b = (const float*)d_in[11];
    const int* adj_row = (const int*)d_in[12];
    const int* adj_col = (const int*)d_in[13];
    float* out = (float*)d_out;

    __half* Xh;  cudaGetSymbolAddress((void**)&Xh, g_Xh);
    __half* H;   cudaGetSymbolAddress((void**)&H, g_H);
    __half* Agg; cudaGetSymbolAddress((void**)&Agg, g_Agg);
    __half* Wh1; cudaGetSymbolAddress((void**)&Wh1, g_Wh1);
    __half* Wh2; cudaGetSymbolAddress((void**)&Wh2, g_Wh2);
    __half* Wh3; cudaGetSymbolAddress((void**)&Wh3, g_Wh3);
    __half* Wh4; cudaGetSymbolAddress((void**)&Wh4, g_Wh4);

    const int GSMEM = 4 * HTILE_HALVES * 2;   // 73728 bytes
    cudaFuncSetAttribute(k_gemm_h, cudaFuncAttributeMaxDynamicSharedMemorySize, GSMEM);

    const int nThreads = 256;
    int nBlkN = (NN + nThreads - 1) / nThreads;
    int nBlkE = (EE + nThreads - 1) / nThreads;
    int prepBlk = (int)((PREP_TOTAL + nThreads - 1) / nThreads);

    dim3 gemmGrid((NN + 127) / 128, 2);
    int spmmBlocks = (NN * 32 + nThreads - 1) / nThreads;

    k_prep<<<prepBlk, nThreads>>>(x, w1, w2, w3, w4, fc_w);
    k_hist<<<nBlkE, nThreads>>>(adj_row);
    k_scan1<<<NSCANBLK, SCAN_BLK>>>();
    k_scan2<<<1, 128>>>();
    k_scan3cur<<<nBlkN, nThreads>>>();
    k_scatter<<<nBlkE, nThreads>>>(adj_row, adj_col, adj_val);

    // Running scale: each spmm multiplies stored values by 1/4 (sigma_l = 4^l).
    k_spmm<128><<<spmmBlocks, nThreads>>>(Xh, Agg);
    k_gemm_h<<<gemmGrid, nThreads, GSMEM>>>(Agg, Wh1, b1, 1.f / 4.f, H, NN, 128);
    k_spmm<256><<<spmmBlocks, nThreads>>>(H, Agg);
    k_gemm_h<<<gemmGrid, nThreads, GSMEM>>>(Agg, Wh2, b2, 1.f / 16.f, H, NN, 256);
    k_spmm<256><<<spmmBlocks, nThreads>>>(H, Agg);
    k_gemm_h<<<gemmGrid, nThreads, GSMEM>>>(Agg, Wh3, b3, 1.f / 64.f, H, NN, 256);
    k_spmm<256><<<spmmBlocks, nThreads>>>(H, Agg);
    k_gemm_h<<<gemmGrid, nThreads, GSMEM>>>(Agg, Wh4, b4, 1.f / 256.f, H, NN, 256);

    int fcBlocks = (NN + 63) / 64;
    k_fc_hmma<<<fcBlocks, 128>>>(H, fc_b, out);
}

// round 15
// speedup vs baseline: 1.3713x; 1.0254x over previous
#include <cuda_runtime.h>
#include <cuda_fp16.h>
#include <math.h>
#include <stdint.h>

#define NN 100000
#define EE 3200000
#define NHID 256
#define NCLASS 16
#define SCAN_BLK 1024
#define NSCANBLK ((NN + SCAN_BLK - 1) / SCAN_BLK)   // 98

// ---------------- scratch (static device globals) ---------------------------
__device__ __half g_Xh[(size_t)NN * 128];   // x in fp16
__device__ __half g_H[(size_t)NN * 256];    // layer activations, fp16 (scaled)
__device__ __half g_Agg[(size_t)NN * 256];  // SpMM output, fp16 (scaled)
__device__ int2   g_cv[EE];                 // packed (col, val) CSR payload
__device__ int    g_rowptr[NN + 1];
__device__ int    g_cursor[NN];
__device__ int    g_blocksums[SCAN_BLK];
__device__ __half g_Wh1[256 * 128];         // weights [n][k] K-major fp16
__device__ __half g_Wh2[256 * 256];
__device__ __half g_Wh3[256 * 256];
__device__ __half g_Wh4[256 * 256];
__device__ __half g_fwT[16 * 256];          // fc_w transposed [n][k] fp16

__device__ __forceinline__ uint32_t smem_u32(const void* p) {
    uint32_t a;
    asm("{ .reg .u64 t; cvta.to.shared.u64 t, %1; cvt.u32.u64 %0, t; }"
        : "=r"(a) : "l"(p));
    return a;
}

__device__ __forceinline__ void cpasync16(uint32_t dst, const void* src) {
    asm volatile("cp.async.ca.shared.global [%0], [%1], 16;" :: "r"(dst), "l"(src));
}

// L2-only (bypass L1) vector loads for the streaming gather
__device__ __forceinline__ uint4 ldg_cg_v4(const void* p) {
    uint4 q;
    asm volatile("ld.global.cg.v4.b32 {%0,%1,%2,%3}, [%4];"
                 : "=r"(q.x), "=r"(q.y), "=r"(q.z), "=r"(q.w) : "l"(p));
    return q;
}
__device__ __forceinline__ uint2 ldg_cg_v2(const void* p) {
    uint2 q;
    asm volatile("ld.global.cg.v2.b32 {%0,%1}, [%2];"
                 : "=r"(q.x), "=r"(q.y) : "l"(p));
    return q;
}

// ---------------- prep: fp16 conversions (NO cursor zero — runs overlapped) --
#define PREP_W1   (256 * 128)
#define PREP_W    (256 * 256)
#define PREP_FW   (16 * 256)
#define PREP_X4   ((long long)NN * 128 / 4)
#define PREP_TOTAL (PREP_W1 + 3LL * PREP_W + PREP_FW + PREP_X4)

__global__ void k_prep(const float* __restrict__ x,
                       const float* __restrict__ w1, const float* __restrict__ w2,
                       const float* __restrict__ w3, const float* __restrict__ w4,
                       const float* __restrict__ fcw) {
    long long i = (long long)blockIdx.x * blockDim.x + threadIdx.x;
    if (i < PREP_W1) {
        int n = (int)(i / 128), k = (int)(i % 128);
        g_Wh1[i] = __float2half_rn(w1[k * 256 + n]);
        return;
    }
    i -= PREP_W1;
    if (i < 3 * PREP_W) {
        int w = (int)(i / PREP_W);
        int r = (int)(i % PREP_W);
        int n = r / 256, k = r % 256;
        if (w == 0) g_Wh2[r] = __float2half_rn(w2[k * 256 + n]);
        else if (w == 1) g_Wh3[r] = __float2half_rn(w3[k * 256 + n]);
        else g_Wh4[r] = __float2half_rn(w4[k * 256 + n]);
        return;
    }
    i -= 3 * PREP_W;
    if (i < PREP_FW) {
        int n = (int)(i / 256), k = (int)(i % 256);
        g_fwT[i] = __float2half_rn(fcw[k * 16 + n]);
        return;
    }
    i -= PREP_FW;
    if (i < PREP_X4) {
        float4 v = ((const float4*)x)[i];
        __half2 h0 = __floats2half2_rn(v.x, v.y);
        __half2 h1 = __floats2half2_rn(v.z, v.w);
        ((uint2*)g_Xh)[i] = make_uint2(*(uint32_t*)&h0, *(uint32_t*)&h1);
    }
}

// ---------------- CSR build --------------------------------------------------
__global__ void k_zero_cnt() {
    int i = blockIdx.x * blockDim.x + threadIdx.x;
    if (i < NN) g_cursor[i] = 0;
}

__global__ void k_hist(const int* __restrict__ row) {
    int e = blockIdx.x * blockDim.x + threadIdx.x;
    if (e < EE) atomicAdd(&g_cursor[row[e]], 1);
}

__global__ void k_scan1() {
    __shared__ int s[SCAN_BLK];
    int t = threadIdx.x;
    int gid = blockIdx.x * SCAN_BLK + t;
    s[t] = (gid < NN) ? g_cursor[gid] : 0;
    for (int d = 1; d < SCAN_BLK; d <<= 1) {
        __syncthreads();
        int u = (t >= d) ? s[t - d] : 0;
        __syncthreads();
        s[t] += u;
    }
    __syncthreads();
    if (gid < NN) g_rowptr[gid + 1] = s[t];
    if (t == SCAN_BLK - 1) g_blocksums[blockIdx.x] = s[t];
}

__global__ void k_scan2() {
    __shared__ int s[128];
    int t = threadIdx.x;
    s[t] = (t < NSCANBLK) ? g_blocksums[t] : 0;
    for (int d = 1; d < 128; d <<= 1) {
        __syncthreads();
        int u = (t >= d) ? s[t - d] : 0;
        __syncthreads();
        s[t] += u;
    }
    __syncthreads();
    if (t < NSCANBLK) g_blocksums[t] = s[t];
}

__global__ void k_scan3cur() {
    int i = blockIdx.x * blockDim.x + threadIdx.x;
    if (i < NN) {
        int b = i >> 10;
        int off = b ? g_blocksums[b - 1] : 0;
        int v = g_rowptr[i + 1] + off;
        g_rowptr[i + 1] = v;
        if (i + 1 < NN) g_cursor[i + 1] = v;
        if (i == 0) { g_rowptr[0] = 0; g_cursor[0] = 0; }
    }
}

__global__ void k_scatter(const int* __restrict__ row, const int* __restrict__ col,
                          const float* __restrict__ val) {
    int e = blockIdx.x * blockDim.x + threadIdx.x;
    if (e < EE) {
        int r = row[e];
        int p = atomicAdd(&g_cursor[r], 1);
        g_cv[p] = make_int2(col[e], __float_as_int(val[e]));
    }
}

// ---------------- SpMM (CSR, fp16 gather -> fp16 out, scaled by 1/4) --------
// One warp per dest node. Full chunks branch-free; remainder clamped.
template <int NC>
__global__ void k_spmm(const __half* __restrict__ S, __half* __restrict__ out) {
    int w = (blockIdx.x * blockDim.x + threadIdx.x) >> 5;
    if (w >= NN) return;
    int lane = threadIdx.x & 31;
    constexpr int HP = NC / 32;

    float acc[HP];
#pragma unroll
    for (int i = 0; i < HP; i++) acc[i] = 0.f;

    int s = g_rowptr[w], e = g_rowptr[w + 1];
    int nfull = (e - s) >> 5;

    // full 32-edge chunks: unconditional cv load, branch-free inner loop
    const int2* cvp = g_cv + s + lane;
    for (int ch = 0; ch < nfull; ch++, cvp += 32) {
        int2 q0 = *cvp;
        int c = q0.x;
        float v = __int_as_float(q0.y);
#pragma unroll 8
        for (int j = 0; j < 32; j++) {
            int cj = __shfl_sync(0xffffffffu, c, j);
            float vj = __shfl_sync(0xffffffffu, v, j);
            if (NC == 256) {
                uint4 q = ldg_cg_v4((const uint4*)S + (size_t)cj * 32 + lane);
                const __half2* h = (const __half2*)&q;
#pragma unroll
                for (int p = 0; p < 4; p++) {
                    float2 f = __half22float2(h[p]);
                    acc[p * 2] += vj * f.x;
                    acc[p * 2 + 1] += vj * f.y;
                }
            } else {
                uint2 q = ldg_cg_v2((const uint2*)S + (size_t)cj * 32 + lane);
                const __half2* h = (const __half2*)&q;
#pragma unroll
                for (int p = 0; p < 2; p++) {
                    float2 f = __half22float2(h[p]);
                    acc[p * 2] += vj * f.x;
                    acc[p * 2 + 1] += vj * f.y;
                }
            }
        }
    }
    // remainder (< 32 edges): clamped cv load, bounded loop
    int base = s + nfull * 32;
    int m = e - base;
    if (m > 0) {
        int idx = base + lane;
        int idxc = min(idx, e - 1);
        int2 q0 = g_cv[idxc];
        int c = q0.x;
        float v = (idx < e) ? __int_as_float(q0.y) : 0.f;
        for (int j = 0; j < m; j++) {
            int cj = __shfl_sync(0xffffffffu, c, j);
            float vj = __shfl_sync(0xffffffffu, v, j);
            if (NC == 256) {
                uint4 q = ldg_cg_v4((const uint4*)S + (size_t)cj * 32 + lane);
                const __half2* h = (const __half2*)&q;
#pragma unroll
                for (int p = 0; p < 4; p++) {
                    float2 f = __half22float2(h[p]);
                    acc[p * 2] += vj * f.x;
                    acc[p * 2 + 1] += vj * f.y;
                }
            } else {
                uint2 q = ldg_cg_v2((const uint2*)S + (size_t)cj * 32 + lane);
                const __half2* h = (const __half2*)&q;
#pragma unroll
                for (int p = 0; p < 2; p++) {
                    float2 f = __half22float2(h[p]);
                    acc[p * 2] += vj * f.x;
                    acc[p * 2 + 1] += vj * f.y;
                }
            }
        }
    }

    const float SC = 0.25f;
    __half2 o[HP / 2];
#pragma unroll
    for (int p = 0; p < HP / 2; p++)
        o[p] = __floats2half2_rn(acc[p * 2] * SC, acc[p * 2 + 1] * SC);
    if (NC == 256)
        ((uint4*)out)[(size_t)w * 32 + lane] = *(uint4*)o;
    else
        ((uint2*)out)[(size_t)w * 32 + lane] = *(uint2*)o;
}

// ---------------- fp16 HMMA GEMM + fused (scaled) bias + relu (R8 version) ---
#define HBK 64
#define HROW 72                        // +8 halves pad (16B)
#define HTILE_HALVES (128 * HROW)      // 9216 halves = 18432 B per tile

__global__ void __launch_bounds__(256, 2) k_gemm_h(
    const __half* __restrict__ A, const __half* __restrict__ Wt,
    const float* __restrict__ bias, float bscale,
    __half* __restrict__ C, int M, int K) {
    extern __shared__ __half sm[];
    uint32_t sb = smem_u32(sm);
    int tid = threadIdx.x;
    int wid = tid >> 5, lane = tid & 31;
    int wm = wid & 1, wn = wid >> 1;
    int gid = lane >> 2, tg = lane & 3;

    int row0 = blockIdx.x * 128;
    int col0 = blockIdx.y * 128;
    int nIter = K / HBK;

    const int aoff[2] = {0, 2 * HTILE_HALVES};
    const int boff[2] = {HTILE_HALVES, 3 * HTILE_HALVES};

    float acc[4][4][4];
#pragma unroll
    for (int i = 0; i < 4; i++)
#pragma unroll
        for (int j = 0; j < 4; j++)
#pragma unroll
            for (int k = 0; k < 4; k++) acc[i][j][k] = 0.f;

    auto stage = [&](int c, int buf) {
        int k0 = c * HBK;
        const __half* Ag = A + (size_t)row0 * K + k0;
#pragma unroll
        for (int it = 0; it < 4; it++) {
            int idx = tid + it * 256;
            int r = idx >> 3, c8 = idx & 7;
            if (row0 + r < M)
                cpasync16(sb + (uint32_t)(aoff[buf] + r * HROW) * 2 + c8 * 16,
                          Ag + (size_t)r * K + c8 * 8);
        }
        const __half* Bg = Wt + (size_t)col0 * K + k0;
#pragma unroll
        for (int it = 0; it < 4; it++) {
            int idx = tid + it * 256;
            int r = idx >> 3, c8 = idx & 7;
            cpasync16(sb + (uint32_t)(boff[buf] + r * HROW) * 2 + c8 * 16,
                      Bg + (size_t)r * K + c8 * 8);
        }
        asm volatile("cp.async.commit_group;" ::: "memory");
    };

    stage(0, 0);

    for (int c = 0; c < nIter; c++) {
        int buf = c & 1;
        if (c + 1 < nIter) {
            stage(c + 1, buf ^ 1);
            asm volatile("cp.async.wait_group 1;" ::: "memory");
        } else {
            asm volatile("cp.async.wait_group 0;" ::: "memory");
        }
        __syncthreads();

        const uint32_t* As = (const uint32_t*)(sm + aoff[buf]);
        const uint32_t* Bs = (const uint32_t*)(sm + boff[buf]);

#pragma unroll
        for (int ks = 0; ks < 4; ks++) {
            int k = ks * 16;
            uint32_t a[4][4], b[4][2];
#pragma unroll
            for (int mt = 0; mt < 4; mt++) {
                int rb = wm * 64 + mt * 16 + gid;
                int base0 = (rb * HROW + k) >> 1;
                int base1 = ((rb + 8) * HROW + k) >> 1;
                a[mt][0] = As[base0 + tg];
                a[mt][1] = As[base1 + tg];
                a[mt][2] = As[base0 + tg + 4];
                a[mt][3] = As[base1 + tg + 4];
            }
#pragma unroll
            for (int nt = 0; nt < 4; nt++) {
                int nb = wn * 32 + nt * 8 + gid;
                int base = (nb * HROW + k) >> 1;
                b[nt][0] = Bs[base + tg];
                b[nt][1] = Bs[base + tg + 4];
            }
#pragma unroll
            for (int mt = 0; mt < 4; mt++)
#pragma unroll
                for (int nt = 0; nt < 4; nt++) {
                    float* d = acc[mt][nt];
                    asm volatile(
                        "mma.sync.aligned.m16n8k16.row.col.f32.f16.f16.f32 "
                        "{%0,%1,%2,%3}, {%4,%5,%6,%7}, {%8,%9}, {%0,%1,%2,%3};"
                        : "+f"(d[0]), "+f"(d[1]), "+f"(d[2]), "+f"(d[3])
                        : "r"(a[mt][0]), "r"(a[mt][1]), "r"(a[mt][2]), "r"(a[mt][3]),
                          "r"(b[nt][0]), "r"(b[nt][1]));
                }
        }
        __syncthreads();
    }

#pragma unroll
    for (int nt = 0; nt < 4; nt++) {
        int cg = col0 + wn * 32 + nt * 8 + tg * 2;
        float bx = bias[cg] * bscale, by = bias[cg + 1] * bscale;
#pragma unroll
        for (int mt = 0; mt < 4; mt++) {
            int rg = row0 + wm * 64 + mt * 16 + gid;
            float* d = acc[mt][nt];
            if (rg < M) {
                float v0 = fmaxf(d[0] + bx, 0.f);
                float v1 = fmaxf(d[1] + by, 0.f);
                *(__half2*)(C + (size_t)rg * 256 + cg) = __floats2half2_rn(v0, v1);
            }
            if (rg + 8 < M) {
                float v2 = fmaxf(d[2] + bx, 0.f);
                float v3 = fmaxf(d[3] + by, 0.f);
                *(__half2*)(C + (size_t)(rg + 8) * 256 + cg) = __floats2half2_rn(v2, v3);
            }
        }
    }
}

// ---------------- HMMA FC + log_softmax (fp16 H at scale 1/256) --------------
__global__ void __launch_bounds__(128) k_fc_hmma(const __half* __restrict__ H,
                                                 const float* __restrict__ fb,
                                                 float* __restrict__ out) {
    __shared__ float sfb[16];
    int tid = threadIdx.x;
    if (tid < 16) sfb[tid] = fb[tid];
    __syncthreads();

    int wid = tid >> 5, lane = tid & 31;
    int gid = lane >> 2, tg = lane & 3;
    int row0 = (blockIdx.x * 4 + wid) * 16;
    if (row0 >= NN) return;

    int rA = row0 + gid;
    int rB = row0 + gid + 8;
    int rAc = min(rA, NN - 1);
    int rBc = min(rB, NN - 1);

    float c0[4] = {0.f, 0.f, 0.f, 0.f};
    float c1[4] = {0.f, 0.f, 0.f, 0.f};

    const __half* HA = H + (size_t)rAc * 256;
    const __half* HB = H + (size_t)rBc * 256;
    const __half* W0 = g_fwT + (size_t)gid * 256;
    const __half* W1 = g_fwT + (size_t)(gid + 8) * 256;

#pragma unroll
    for (int kc = 0; kc < 16; kc++) {
        int k = kc * 16;
        uint32_t a0 = *(const uint32_t*)(HA + k + 2 * tg);
        uint32_t a1 = *(const uint32_t*)(HB + k + 2 * tg);
        uint32_t a2 = *(const uint32_t*)(HA + k + 2 * tg + 8);
        uint32_t a3 = *(const uint32_t*)(HB + k + 2 * tg + 8);
        uint32_t b00 = *(const uint32_t*)(W0 + k + 2 * tg);
        uint32_t b01 = *(const uint32_t*)(W0 + k + 2 * tg + 8);
        uint32_t b10 = *(const uint32_t*)(W1 + k + 2 * tg);
        uint32_t b11 = *(const uint32_t*)(W1 + k + 2 * tg + 8);
        asm volatile(
            "mma.sync.aligned.m16n8k16.row.col.f32.f16.f16.f32 "
            "{%0,%1,%2,%3}, {%4,%5,%6,%7}, {%8,%9}, {%0,%1,%2,%3};"
            : "+f"(c0[0]), "+f"(c0[1]), "+f"(c0[2]), "+f"(c0[3])
            : "r"(a0), "r"(a1), "r"(a2), "r"(a3), "r"(b00), "r"(b01));
        asm volatile(
            "mma.sync.aligned.m16n8k16.row.col.f32.f16.f16.f32 "
            "{%0,%1,%2,%3}, {%4,%5,%6,%7}, {%8,%9}, {%0,%1,%2,%3};"
            : "+f"(c1[0]), "+f"(c1[1]), "+f"(c1[2]), "+f"(c1[3])
            : "r"(a0), "r"(a1), "r"(a2), "r"(a3), "r"(b10), "r"(b11));
    }

    float fb0 = sfb[2 * tg], fb1 = sfb[2 * tg + 1];
    float fb2 = sfb[8 + 2 * tg], fb3 = sfb[8 + 2 * tg + 1];

#pragma unroll
    for (int rr = 0; rr < 2; rr++) {
        int row = rr ? rB : rA;
        float v0 = (rr ? c0[2] : c0[0]) * 256.f + fb0;
        float v1 = (rr ? c0[3] : c0[1]) * 256.f + fb1;
        float v2 = (rr ? c1[2] : c1[0]) * 256.f + fb2;
        float v3 = (rr ? c1[3] : c1[1]) * 256.f + fb3;
        float mx = fmaxf(fmaxf(v0, v1), fmaxf(v2, v3));
        mx = fmaxf(mx, __shfl_xor_sync(0xffffffffu, mx, 1));
        mx = fmaxf(mx, __shfl_xor_sync(0xffffffffu, mx, 2));
        float sm = expf(v0 - mx) + expf(v1 - mx) + expf(v2 - mx) + expf(v3 - mx);
        sm += __shfl_xor_sync(0xffffffffu, sm, 1);
        sm += __shfl_xor_sync(0xffffffffu, sm, 2);
        float ls = logf(sm);
        if (row < NN) {
            float* o = out + (size_t)row * 16;
            *(float2*)(o + 2 * tg) = make_float2((v0 - mx) - ls, (v1 - mx) - ls);
            *(float2*)(o + 8 + 2 * tg) = make_float2((v2 - mx) - ls, (v3 - mx) - ls);
        }
    }
}

// ---------------- launch -----------------------------------------------------
extern "C" void kernel_launch(void* const* d_in, const int* in_sizes, int n_in,
                              void* d_out, int out_size) {
    const float* x    = (const float*)d_in[0];
    const float* adj_val = (const float*)d_in[1];
    const float* w1 = (const float*)d_in[2];
    const float* b1 = (const float*)d_in[3];
    const float* w2 = (const float*)d_in[4];
    const float* b2 = (const float*)d_in[5];
    const float* w3 = (const float*)d_in[6];
    const float* b3 = (const float*)d_in[7];
    const float* w4 = (const float*)d_in[8];
    const float* b4 = (const float*)d_in[9];
    const float* fc_w = (const float*)d_in[10];
    const float* fc_b = (const float*)d_in[11];
    const int* adj_row = (const int*)d_in[12];
    const int* adj_col = (const int*)d_in[13];
    float* out = (float*)d_out;

    __half* Xh;  cudaGetSymbolAddress((void**)&Xh, g_Xh);
    __half* H;   cudaGetSymbolAddress((void**)&H, g_H);
    __half* Agg; cudaGetSymbolAddress((void**)&Agg, g_Agg);
    __half* Wh1; cudaGetSymbolAddress((void**)&Wh1, g_Wh1);
    __half* Wh2; cudaGetSymbolAddress((void**)&Wh2, g_Wh2);
    __half* Wh3; cudaGetSymbolAddress((void**)&Wh3, g_Wh3);
    __half* Wh4; cudaGetSymbolAddress((void**)&Wh4, g_Wh4);

    const int GSMEM = 4 * HTILE_HALVES * 2;   // 73728 bytes
    cudaFuncSetAttribute(k_gemm_h, cudaFuncAttributeMaxDynamicSharedMemorySize, GSMEM);

    const int nThreads = 256;
    int nBlkN = (NN + nThreads - 1) / nThreads;
    int nBlkE = (EE + nThreads - 1) / nThreads;
    int prepBlk = (int)((PREP_TOTAL + nThreads - 1) / nThreads);

    dim3 gemmGrid((NN + 127) / 128, 2);
    int spmmBlocks = (NN * 32 + nThreads - 1) / nThreads;

    // ---- fork: prep (fp16 conversions) runs parallel to the CSR chain ----
    cudaStream_t s2;
    cudaEvent_t evFork, evJoin;
    cudaStreamCreateWithFlags(&s2, cudaStreamNonBlocking);
    cudaEventCreateWithFlags(&evFork, cudaEventDisableTiming);
    cudaEventCreateWithFlags(&evJoin, cudaEventDisableTiming);

    cudaEventRecord(evFork, 0);
    cudaStreamWaitEvent(s2, evFork, 0);
    k_prep<<<prepBlk, nThreads, 0, s2>>>(x, w1, w2, w3, w4, fc_w);
    cudaEventRecord(evJoin, s2);

    // CSR chain on the capture (default) stream
    k_zero_cnt<<<nBlkN, nThreads>>>();
    k_hist<<<nBlkE, nThreads>>>(adj_row);
    k_scan1<<<NSCANBLK, SCAN_BLK>>>();
    k_scan2<<<1, 128>>>();
    k_scan3cur<<<nBlkN, nThreads>>>();
    k_scatter<<<nBlkE, nThreads>>>(adj_row, adj_col, adj_val);

    cudaStreamWaitEvent(0, evJoin, 0);   // join: layers need Xh/weights + CSR

    // Running scale: each spmm multiplies stored values by 1/4 (sigma_l = 4^l).
    k_spmm<128><<<spmmBlocks, nThreads>>>(Xh, Agg);
    k_gemm_h<<<gemmGrid, nThreads, GSMEM>>>(Agg, Wh1, b1, 1.f / 4.f, H, NN, 128);
    k_spmm<256><<<spmmBlocks, nThreads>>>(H, Agg);
    k_gemm_h<<<gemmGrid, nThreads, GSMEM>>>(Agg, Wh2, b2, 1.f / 16.f, H, NN, 256);
    k_spmm<256><<<spmmBlocks, nThreads>>>(H, Agg);
    k_gemm_h<<<gemmGrid, nThreads, GSMEM>>>(Agg, Wh3, b3, 1.f / 64.f, H, NN, 256);
    k_spmm<256><<<spmmBlocks, nThreads>>>(H, Agg);
    k_gemm_h<<<gemmGrid, nThreads, GSMEM>>>(Agg, Wh4, b4, 1.f / 256.f, H, NN, 256);

    int fcBlocks = (NN + 63) / 64;
    k_fc_hmma<<<fcBlocks, 128>>>(H, fc_b, out);

    cudaEventDestroy(evFork);
    cudaEventDestroy(evJoin);
    cudaStreamDestroy(s2);
}